// round 1
// baseline (speedup 1.0000x reference)
#include <cuda_runtime.h>
#include <math.h>

#define NN 100000
#define HH 128

// ---- static device scratch (no allocation allowed) ----
__device__ float g_h[(size_t)NN * HH];     // XW result (reused both layers)
__device__ float g_aggA[(size_t)NN * HH];  // layer-1 aggregate
__device__ float g_aggB[(size_t)NN * HH];  // layer-2 aggregate
__device__ int   g_deg[NN];
__device__ float g_dinv[NN];

// ---------------------------------------------------------------------------
__global__ void zero_deg_kernel(int n) {
    int i = blockIdx.x * blockDim.x + threadIdx.x;
    if (i < n) g_deg[i] = 0;
}

__global__ void deg_count_kernel(const int* __restrict__ dst, int e) {
    int i = blockIdx.x * blockDim.x + threadIdx.x;
    if (i < e) atomicAdd(&g_deg[dst[i]], 1);
}

__global__ void dinv_kernel(int n) {
    int i = blockIdx.x * blockDim.x + threadIdx.x;
    if (i < n) g_dinv[i] = rsqrtf((float)g_deg[i] + 1.0f);
}

// ---------------------------------------------------------------------------
// GEMM: h_out[r][c] = sum_k X[r][k] * W[k][c]   (optionally relu(X) on load)
// Also writes agg_out[r][c] = h*dinv[r]^2 + bias[c]  (self-loop init + bias)
// Block: 256 threads -> 32 rows x 128 cols, 16 cols per thread.
#define GEMM_SMEM (HH*HH*4 + 32*129*4)
__global__ __launch_bounds__(256) void gemm_kernel(
    const float* __restrict__ X, const float* __restrict__ W,
    const float* __restrict__ bias, const float* __restrict__ dinv,
    float* __restrict__ h_out, float* __restrict__ agg_out,
    int nrows, int relu_in)
{
    extern __shared__ float smem[];
    float*  Wsh = smem;            // 128*128 floats
    float*  xs  = smem + HH * HH;  // 32*129 floats (padded rows)
    float4* Wshv = (float4*)Wsh;

    int t = threadIdx.x;
    const float4* Wv = (const float4*)W;
    for (int idx = t; idx < HH * HH / 4; idx += 256) Wshv[idx] = Wv[idx];

    int row0 = blockIdx.x * 32;
    for (int idx = t; idx < 32 * 32; idx += 256) {
        int r = idx >> 5, c4 = idx & 31;
        float4 v = make_float4(0.f, 0.f, 0.f, 0.f);
        int gr = row0 + r;
        if (gr < nrows) v = ((const float4*)X)[(size_t)gr * 32 + c4];
        if (relu_in) {
            v.x = fmaxf(v.x, 0.f); v.y = fmaxf(v.y, 0.f);
            v.z = fmaxf(v.z, 0.f); v.w = fmaxf(v.w, 0.f);
        }
        float* xr = xs + r * 129 + c4 * 4;
        xr[0] = v.x; xr[1] = v.y; xr[2] = v.z; xr[3] = v.w;
    }
    __syncthreads();

    int cg = t & 7;    // col group: cols [cg*16, cg*16+16)
    int rl = t >> 3;   // local row 0..31
    float acc[16];
#pragma unroll
    for (int c = 0; c < 16; c++) acc[c] = 0.f;

    const float* xrow = xs + rl * 129;
#pragma unroll 4
    for (int k = 0; k < HH; k++) {
        float a = xrow[k];
        float4 w0 = Wshv[k * 32 + cg * 4 + 0];
        float4 w1 = Wshv[k * 32 + cg * 4 + 1];
        float4 w2 = Wshv[k * 32 + cg * 4 + 2];
        float4 w3 = Wshv[k * 32 + cg * 4 + 3];
        acc[0]  += a * w0.x; acc[1]  += a * w0.y; acc[2]  += a * w0.z; acc[3]  += a * w0.w;
        acc[4]  += a * w1.x; acc[5]  += a * w1.y; acc[6]  += a * w1.z; acc[7]  += a * w1.w;
        acc[8]  += a * w2.x; acc[9]  += a * w2.y; acc[10] += a * w2.z; acc[11] += a * w2.w;
        acc[12] += a * w3.x; acc[13] += a * w3.y; acc[14] += a * w3.z; acc[15] += a * w3.w;
    }

    int gr = row0 + rl;
    if (gr < nrows) {
        float dv = dinv[gr];
        float d2 = dv * dv;
        size_t base4 = (size_t)gr * 32 + cg * 4;
        const float4* bv = (const float4*)bias;
#pragma unroll
        for (int q = 0; q < 4; q++) {
            float4 hv = make_float4(acc[q*4+0], acc[q*4+1], acc[q*4+2], acc[q*4+3]);
            ((float4*)h_out)[base4 + q] = hv;
            float4 bb = bv[cg * 4 + q];
            float4 av = make_float4(hv.x * d2 + bb.x, hv.y * d2 + bb.y,
                                    hv.z * d2 + bb.z, hv.w * d2 + bb.w);
            ((float4*)agg_out)[base4 + q] = av;
        }
    }
}

// ---------------------------------------------------------------------------
// Edge aggregation: agg[dst] += h[src] * (dinv[src]*dinv[dst]); one warp/edge.
__global__ __launch_bounds__(256) void edge_kernel(
    const int* __restrict__ src, const int* __restrict__ dst,
    const float* __restrict__ dinv, const float* __restrict__ h,
    float* __restrict__ agg, int e)
{
    int gid  = blockIdx.x * blockDim.x + threadIdx.x;
    int warp = gid >> 5;
    int lane = threadIdx.x & 31;
    if (warp >= e) return;
    int s = src[warp];
    int d = dst[warp];
    float w = dinv[s] * dinv[d];
    float4 v = ((const float4*)h)[(size_t)s * 32 + lane];
    v.x *= w; v.y *= w; v.z *= w; v.w *= w;
    float* p = agg + (size_t)d * HH + lane * 4;
    asm volatile("red.relaxed.gpu.global.add.v4.f32 [%0], {%1,%2,%3,%4};"
                 :: "l"(p), "f"(v.x), "f"(v.y), "f"(v.z), "f"(v.w) : "memory");
}

// ---------------------------------------------------------------------------
// Pair prediction: sigmoid([h[i], h[j]] @ W_lin + b_lin); one warp/pair.
__global__ __launch_bounds__(256) void pair_kernel(
    const int* __restrict__ pi, const int* __restrict__ pj,
    const float* __restrict__ h, const float* __restrict__ Wl,
    const float* __restrict__ bl, float* __restrict__ out, int p)
{
    int gid  = blockIdx.x * blockDim.x + threadIdx.x;
    int warp = gid >> 5;
    int lane = threadIdx.x & 31;
    if (warp >= p) return;
    int a = pi[warp];
    int b = pj[warp];
    float4 ha = ((const float4*)h)[(size_t)a * 32 + lane];
    float4 hb = ((const float4*)h)[(size_t)b * 32 + lane];
    float4 wa = ((const float4*)Wl)[lane];
    float4 wb = ((const float4*)Wl)[32 + lane];
    float s = ha.x * wa.x + ha.y * wa.y + ha.z * wa.z + ha.w * wa.w
            + hb.x * wb.x + hb.y * wb.y + hb.z * wb.z + hb.w * wb.w;
#pragma unroll
    for (int o = 16; o; o >>= 1) s += __shfl_xor_sync(0xFFFFFFFFu, s, o);
    if (lane == 0) {
        float z = s + bl[0];
        out[warp] = 1.0f / (1.0f + expf(-z));
    }
}

// ---------------------------------------------------------------------------
extern "C" void kernel_launch(void* const* d_in, const int* in_sizes, int n_in,
                              void* d_out, int out_size)
{
    const float* x  = (const float*)d_in[0];
    const int*   ei = (const int*)d_in[1];
    const int*   pi = (const int*)d_in[2];
    const int*   pj = (const int*)d_in[3];
    const float* W1 = (const float*)d_in[4];
    const float* b1 = (const float*)d_in[5];
    const float* W2 = (const float*)d_in[6];
    const float* b2 = (const float*)d_in[7];
    const float* Wl = (const float*)d_in[8];
    const float* bl = (const float*)d_in[9];
    float* out = (float*)d_out;

    int n = in_sizes[0] / HH;
    int e = in_sizes[1] / 2;
    int p = in_sizes[2];
    const int* src  = ei;
    const int* dstp = ei + e;

    float *h_ptr, *aggA, *aggB, *dinvp;
    cudaGetSymbolAddress((void**)&h_ptr, g_h);
    cudaGetSymbolAddress((void**)&aggA,  g_aggA);
    cudaGetSymbolAddress((void**)&aggB,  g_aggB);
    cudaGetSymbolAddress((void**)&dinvp, g_dinv);

    cudaFuncSetAttribute(gemm_kernel, cudaFuncAttributeMaxDynamicSharedMemorySize,
                         GEMM_SMEM);

    // degree + dinv
    zero_deg_kernel<<<(n + 255) / 256, 256>>>(n);
    deg_count_kernel<<<(e + 255) / 256, 256>>>(dstp, e);
    dinv_kernel<<<(n + 255) / 256, 256>>>(n);

    int gemm_blocks = (n + 31) / 32;
    long long ethreads = (long long)e * 32;
    int eblocks = (int)((ethreads + 255) / 256);
    long long pthreads = (long long)p * 32;
    int pblocks = (int)((pthreads + 255) / 256);

    // layer 1: h = x@W1 ; agg = dinv^2*h + b1 ; += messages
    gemm_kernel<<<gemm_blocks, 256, GEMM_SMEM>>>(x, W1, b1, dinvp, h_ptr, aggA, n, 0);
    edge_kernel<<<eblocks, 256>>>(src, dstp, dinvp, h_ptr, aggA, e);

    // layer 2: h2 = relu(agg1)@W2 ; agg2 = dinv^2*h2 + b2 ; += messages
    gemm_kernel<<<gemm_blocks, 256, GEMM_SMEM>>>(aggA, W2, b2, dinvp, h_ptr, aggB, n, 1);
    edge_kernel<<<eblocks, 256>>>(src, dstp, dinvp, h_ptr, aggB, e);

    // pair prediction
    pair_kernel<<<pblocks, 256>>>(pi, pj, aggB, Wl, bl, out, p);
}

// round 2
// speedup vs baseline: 2.9346x; 2.9346x over previous
#include <cuda_runtime.h>
#include <math.h>

#define NN 100000
#define HH 128
#define CHUNK 64

// ---- static device scratch (no allocation allowed) ----
__device__ float g_h[(size_t)NN * HH];     // XW result (reused both layers)
__device__ float g_aggA[(size_t)NN * HH];  // layer-1 aggregate
__device__ float g_aggB[(size_t)NN * HH];  // layer-2 aggregate
__device__ int   g_deg[NN];
__device__ float g_dinv[NN];

// ---------------------------------------------------------------------------
__global__ void zero_deg_kernel(int n) {
    int i = blockIdx.x * blockDim.x + threadIdx.x;
    if (i < n) g_deg[i] = 0;
}

__global__ void deg_count_kernel(const int* __restrict__ dst, int e) {
    int i = blockIdx.x * blockDim.x + threadIdx.x;
    if (i < e) atomicAdd(&g_deg[dst[i]], 1);
}

__global__ void dinv_kernel(int n) {
    int i = blockIdx.x * blockDim.x + threadIdx.x;
    if (i < n) g_dinv[i] = rsqrtf((float)g_deg[i] + 1.0f);
}

// ---------------------------------------------------------------------------
// Register-blocked GEMM: 128x128 tile / block, 8x8 per thread, K in 2 chunks.
// h_out = (relu?)X @ W ; agg_out = h*dinv^2 + bias  (self-loop init + bias)
#define GEMM_SMEM ((128 * CHUNK + CHUNK * 128) * 4)
__global__ __launch_bounds__(256, 2) void gemm_kernel(
    const float* __restrict__ X, const float* __restrict__ W,
    const float* __restrict__ bias, const float* __restrict__ dinv,
    float* __restrict__ h_out, float* __restrict__ agg_out,
    int nrows, int relu_in)
{
    extern __shared__ float smem[];
    float* Xs = smem;               // [128][CHUNK] row-major
    float* Ws = smem + 128 * CHUNK; // [CHUNK][128] row-major

    int t  = threadIdx.x;
    int tx = t & 15;        // col group: 8 cols at tx*8
    int ty = t >> 4;        // row group: 8 rows at ty*8
    int m0 = ty * 8, n0 = tx * 8;
    int row0 = blockIdx.x * 128;

    float acc[8][8];
#pragma unroll
    for (int i = 0; i < 8; i++)
#pragma unroll
        for (int j = 0; j < 8; j++) acc[i][j] = 0.f;

    for (int c0 = 0; c0 < HH; c0 += CHUNK) {
        // load X tile [128][CHUNK] (coalesced float4)
        for (int idx = t; idx < 128 * CHUNK / 4; idx += 256) {
            int r = idx >> 4, kq = idx & 15;
            int gr = row0 + r;
            float4 v = make_float4(0.f, 0.f, 0.f, 0.f);
            if (gr < nrows) v = ((const float4*)X)[(size_t)gr * 32 + (c0 >> 2) + kq];
            if (relu_in) {
                v.x = fmaxf(v.x, 0.f); v.y = fmaxf(v.y, 0.f);
                v.z = fmaxf(v.z, 0.f); v.w = fmaxf(v.w, 0.f);
            }
            ((float4*)Xs)[r * 16 + kq] = v;
        }
        // load W tile [CHUNK][128]
        for (int idx = t; idx < CHUNK * 128 / 4; idx += 256) {
            int k = idx >> 5, nq = idx & 31;
            ((float4*)Ws)[k * 32 + nq] = ((const float4*)W)[(size_t)(c0 + k) * 32 + nq];
        }
        __syncthreads();

#pragma unroll 4
        for (int k = 0; k < CHUNK; k++) {
            float a[8], b[8];
            float4 b0 = ((float4*)Ws)[k * 32 + tx * 2];
            float4 b1 = ((float4*)Ws)[k * 32 + tx * 2 + 1];
            b[0] = b0.x; b[1] = b0.y; b[2] = b0.z; b[3] = b0.w;
            b[4] = b1.x; b[5] = b1.y; b[6] = b1.z; b[7] = b1.w;
#pragma unroll
            for (int i = 0; i < 8; i++) a[i] = Xs[(m0 + i) * CHUNK + k];
#pragma unroll
            for (int i = 0; i < 8; i++)
#pragma unroll
                for (int j = 0; j < 8; j++) acc[i][j] += a[i] * b[j];
        }
        __syncthreads();
    }

    // epilogue: write h and agg = h*dinv^2 + bias
    float4 bb0 = ((const float4*)bias)[tx * 2];
    float4 bb1 = ((const float4*)bias)[tx * 2 + 1];
#pragma unroll
    for (int i = 0; i < 8; i++) {
        int gr = row0 + m0 + i;
        if (gr < nrows) {
            float dv = dinv[gr];
            float d2 = dv * dv;
            size_t base4 = (size_t)gr * 32 + tx * 2;
            float4 h0 = make_float4(acc[i][0], acc[i][1], acc[i][2], acc[i][3]);
            float4 h1 = make_float4(acc[i][4], acc[i][5], acc[i][6], acc[i][7]);
            ((float4*)h_out)[base4]     = h0;
            ((float4*)h_out)[base4 + 1] = h1;
            float4 a0 = make_float4(h0.x * d2 + bb0.x, h0.y * d2 + bb0.y,
                                    h0.z * d2 + bb0.z, h0.w * d2 + bb0.w);
            float4 a1 = make_float4(h1.x * d2 + bb1.x, h1.y * d2 + bb1.y,
                                    h1.z * d2 + bb1.z, h1.w * d2 + bb1.w);
            ((float4*)agg_out)[base4]     = a0;
            ((float4*)agg_out)[base4 + 1] = a1;
        }
    }
}

// ---------------------------------------------------------------------------
// Edge aggregation: agg[dst] += h[src] * (dinv[src]*dinv[dst]); one warp/edge.
__global__ __launch_bounds__(256) void edge_kernel(
    const int* __restrict__ src, const int* __restrict__ dst,
    const float* __restrict__ dinv, const float* __restrict__ h,
    float* __restrict__ agg, int e)
{
    int gid  = blockIdx.x * blockDim.x + threadIdx.x;
    int warp = gid >> 5;
    int lane = threadIdx.x & 31;
    if (warp >= e) return;
    int s = src[warp];
    int d = dst[warp];
    float w = dinv[s] * dinv[d];
    float4 v = ((const float4*)h)[(size_t)s * 32 + lane];
    v.x *= w; v.y *= w; v.z *= w; v.w *= w;
    float* p = agg + (size_t)d * HH + lane * 4;
    asm volatile("red.relaxed.gpu.global.add.v4.f32 [%0], {%1,%2,%3,%4};"
                 :: "l"(p), "f"(v.x), "f"(v.y), "f"(v.z), "f"(v.w) : "memory");
}

// ---------------------------------------------------------------------------
// Pair prediction: sigmoid([h[i], h[j]] @ W_lin + b_lin); one warp/pair.
__global__ __launch_bounds__(256) void pair_kernel(
    const int* __restrict__ pi, const int* __restrict__ pj,
    const float* __restrict__ h, const float* __restrict__ Wl,
    const float* __restrict__ bl, float* __restrict__ out, int p)
{
    int gid  = blockIdx.x * blockDim.x + threadIdx.x;
    int warp = gid >> 5;
    int lane = threadIdx.x & 31;
    if (warp >= p) return;
    int a = pi[warp];
    int b = pj[warp];
    float4 ha = ((const float4*)h)[(size_t)a * 32 + lane];
    float4 hb = ((const float4*)h)[(size_t)b * 32 + lane];
    float4 wa = ((const float4*)Wl)[lane];
    float4 wb = ((const float4*)Wl)[32 + lane];
    float s = ha.x * wa.x + ha.y * wa.y + ha.z * wa.z + ha.w * wa.w
            + hb.x * wb.x + hb.y * wb.y + hb.z * wb.z + hb.w * wb.w;
#pragma unroll
    for (int o = 16; o; o >>= 1) s += __shfl_xor_sync(0xFFFFFFFFu, s, o);
    if (lane == 0) {
        float z = s + bl[0];
        out[warp] = 1.0f / (1.0f + expf(-z));
    }
}

// ---------------------------------------------------------------------------
extern "C" void kernel_launch(void* const* d_in, const int* in_sizes, int n_in,
                              void* d_out, int out_size)
{
    const float* x  = (const float*)d_in[0];
    const int*   ei = (const int*)d_in[1];
    const int*   pi = (const int*)d_in[2];
    const int*   pj = (const int*)d_in[3];
    const float* W1 = (const float*)d_in[4];
    const float* b1 = (const float*)d_in[5];
    const float* W2 = (const float*)d_in[6];
    const float* b2 = (const float*)d_in[7];
    const float* Wl = (const float*)d_in[8];
    const float* bl = (const float*)d_in[9];
    float* out = (float*)d_out;

    int n = in_sizes[0] / HH;
    int e = in_sizes[1] / 2;
    int p = in_sizes[2];
    const int* src  = ei;
    const int* dstp = ei + e;

    float *h_ptr, *aggA, *aggB, *dinvp;
    cudaGetSymbolAddress((void**)&h_ptr, g_h);
    cudaGetSymbolAddress((void**)&aggA,  g_aggA);
    cudaGetSymbolAddress((void**)&aggB,  g_aggB);
    cudaGetSymbolAddress((void**)&dinvp, g_dinv);

    cudaFuncSetAttribute(gemm_kernel, cudaFuncAttributeMaxDynamicSharedMemorySize,
                         GEMM_SMEM);

    // degree + dinv
    zero_deg_kernel<<<(n + 255) / 256, 256>>>(n);
    deg_count_kernel<<<(e + 255) / 256, 256>>>(dstp, e);
    dinv_kernel<<<(n + 255) / 256, 256>>>(n);

    int gemm_blocks = (n + 127) / 128;
    long long ethreads = (long long)e * 32;
    int eblocks = (int)((ethreads + 255) / 256);
    long long pthreads = (long long)p * 32;
    int pblocks = (int)((pthreads + 255) / 256);

    // layer 1: h = x@W1 ; agg = dinv^2*h + b1 ; += messages
    gemm_kernel<<<gemm_blocks, 256, GEMM_SMEM>>>(x, W1, b1, dinvp, h_ptr, aggA, n, 0);
    edge_kernel<<<eblocks, 256>>>(src, dstp, dinvp, h_ptr, aggA, e);

    // layer 2: h2 = relu(agg1)@W2 ; agg2 = dinv^2*h2 + b2 ; += messages
    gemm_kernel<<<gemm_blocks, 256, GEMM_SMEM>>>(aggA, W2, b2, dinvp, h_ptr, aggB, n, 1);
    edge_kernel<<<eblocks, 256>>>(src, dstp, dinvp, h_ptr, aggB, e);

    // pair prediction
    pair_kernel<<<pblocks, 256>>>(pi, pj, aggB, Wl, bl, out, p);
}

// round 4
// speedup vs baseline: 5.2603x; 1.7925x over previous
#include <cuda_runtime.h>
#include <math.h>

#define NN 100000
#define EE 1600000
#define HH 128
#define CHUNK 64

// ---- static device scratch (no allocation allowed) ----
__device__ float g_h[(size_t)NN * HH];     // XW result (reused both layers)
__device__ float g_aggA[(size_t)NN * HH];  // layer-1 aggregate
__device__ float g_aggB[(size_t)NN * HH];  // layer-2 aggregate
__device__ int   g_deg[NN];
__device__ float g_dinv[NN];
__device__ int   g_off[NN + 1];
__device__ int   g_cur[NN];
__device__ int   g_csr[EE];
__device__ int   g_bsum[512];
__device__ float g_u[NN];
__device__ float g_v[NN];

// ---------------------------------------------------------------------------
__global__ void zero_deg_kernel(int n) {
    int i = blockIdx.x * blockDim.x + threadIdx.x;
    if (i < n) g_deg[i] = 0;
}

__global__ void deg_count_kernel(const int* __restrict__ dst, int e) {
    int i = blockIdx.x * blockDim.x + threadIdx.x;
    if (i < e) atomicAdd(&g_deg[dst[i]], 1);
}

__global__ void dinv_kernel(int n) {
    int i = blockIdx.x * blockDim.x + threadIdx.x;
    if (i < n) g_dinv[i] = rsqrtf((float)g_deg[i] + 1.0f);
}

// ---- exclusive prefix scan of deg into off (off[0]=0, off[i+1]=sum<=i) ----
__global__ __launch_bounds__(256) void scan1_kernel(int n) {
    __shared__ int wsum[8];
    __shared__ int woff[8];
    int t = threadIdx.x;
    int base = blockIdx.x * 1024;
    int idx0 = base + t * 4;
    int v[4];
#pragma unroll
    for (int q = 0; q < 4; q++) {
        int i = idx0 + q;
        v[q] = (i < n) ? g_deg[i] : 0;
    }
    v[1] += v[0]; v[2] += v[1]; v[3] += v[2];
    int tsum = v[3];
    int lane = t & 31, wid = t >> 5;
    int x = tsum;
#pragma unroll
    for (int o = 1; o < 32; o <<= 1) {
        int y = __shfl_up_sync(0xFFFFFFFFu, x, o);
        if (lane >= o) x += y;
    }
    if (lane == 31) wsum[wid] = x;
    __syncthreads();
    if (t == 0) {
        int a = 0;
        for (int w = 0; w < 8; w++) { woff[w] = a; a += wsum[w]; }
    }
    __syncthreads();
    int ex = x - tsum + woff[wid];
#pragma unroll
    for (int q = 0; q < 4; q++) {
        int i = idx0 + q;
        if (i < n) g_off[i + 1] = ex + v[q];
    }
    if (t == 255) g_bsum[blockIdx.x] = ex + tsum;
}

__global__ __launch_bounds__(256) void scan2_kernel(int nb) {
    __shared__ int ws[8];
    int t = threadIdx.x;
    int x = (t < nb) ? g_bsum[t] : 0;
    int lane = t & 31, wid = t >> 5;
#pragma unroll
    for (int o = 1; o < 32; o <<= 1) {
        int y = __shfl_up_sync(0xFFFFFFFFu, x, o);
        if (lane >= o) x += y;
    }
    if (lane == 31) ws[wid] = x;
    __syncthreads();
    int add = 0;
    for (int w = 0; w < wid; w++) add += ws[w];
    x += add;
    if (t < nb) g_bsum[t] = x;   // inclusive block sums
}

__global__ __launch_bounds__(256) void scan3_kernel(int n) {
    int b = blockIdx.x;
    int add = (b == 0) ? 0 : g_bsum[b - 1];
    int idx0 = b * 1024 + threadIdx.x * 4;
    if (b == 0 && threadIdx.x == 0) g_off[0] = 0;
#pragma unroll
    for (int q = 0; q < 4; q++) {
        int i = idx0 + q;
        if (i < n) {
            int o = g_off[i + 1] + add;
            g_off[i + 1] = o;
        }
    }
}

__global__ void init_cur_kernel(int n) {
    int i = blockIdx.x * blockDim.x + threadIdx.x;
    if (i < n) g_cur[i] = g_off[i];
}

__global__ void scatter_kernel(const int* __restrict__ src,
                               const int* __restrict__ dst, int e) {
    int i = blockIdx.x * blockDim.x + threadIdx.x;
    if (i < e) {
        int d = dst[i];
        int pos = atomicAdd(&g_cur[d], 1);
        g_csr[pos] = src[i];
    }
}

// ---------------------------------------------------------------------------
// Register-blocked GEMM: 128x128 tile / block, 8x8 per thread, K in 2 chunks.
// h_out = (relu?)X @ W
#define GEMM_SMEM ((128 * CHUNK + CHUNK * 128) * 4)
__global__ __launch_bounds__(256, 2) void gemm_kernel(
    const float* __restrict__ X, const float* __restrict__ W,
    float* __restrict__ h_out, int nrows, int relu_in)
{
    extern __shared__ float smem[];
    float* Xs = smem;               // [128][CHUNK]
    float* Ws = smem + 128 * CHUNK; // [CHUNK][128]

    int t  = threadIdx.x;
    int tx = t & 15;        // 8 cols at tx*8
    int ty = t >> 4;        // 8 rows at ty*8
    int m0 = ty * 8;
    int row0 = blockIdx.x * 128;

    float acc[8][8];
#pragma unroll
    for (int i = 0; i < 8; i++)
#pragma unroll
        for (int j = 0; j < 8; j++) acc[i][j] = 0.f;

    for (int c0 = 0; c0 < HH; c0 += CHUNK) {
        for (int idx = t; idx < 128 * CHUNK / 4; idx += 256) {
            int r = idx >> 4, kq = idx & 15;
            int gr = row0 + r;
            float4 v = make_float4(0.f, 0.f, 0.f, 0.f);
            if (gr < nrows) v = ((const float4*)X)[(size_t)gr * 32 + (c0 >> 2) + kq];
            if (relu_in) {
                v.x = fmaxf(v.x, 0.f); v.y = fmaxf(v.y, 0.f);
                v.z = fmaxf(v.z, 0.f); v.w = fmaxf(v.w, 0.f);
            }
            ((float4*)Xs)[r * 16 + kq] = v;
        }
        for (int idx = t; idx < CHUNK * 128 / 4; idx += 256) {
            int k = idx >> 5, nq = idx & 31;
            ((float4*)Ws)[k * 32 + nq] = ((const float4*)W)[(size_t)(c0 + k) * 32 + nq];
        }
        __syncthreads();

#pragma unroll 4
        for (int k = 0; k < CHUNK; k++) {
            float a[8], b[8];
            float4 b0 = ((float4*)Ws)[k * 32 + tx * 2];
            float4 b1 = ((float4*)Ws)[k * 32 + tx * 2 + 1];
            b[0] = b0.x; b[1] = b0.y; b[2] = b0.z; b[3] = b0.w;
            b[4] = b1.x; b[5] = b1.y; b[6] = b1.z; b[7] = b1.w;
#pragma unroll
            for (int i = 0; i < 8; i++) a[i] = Xs[(m0 + i) * CHUNK + k];
#pragma unroll
            for (int i = 0; i < 8; i++)
#pragma unroll
                for (int j = 0; j < 8; j++) acc[i][j] += a[i] * b[j];
        }
        __syncthreads();
    }

#pragma unroll
    for (int i = 0; i < 8; i++) {
        int gr = row0 + m0 + i;
        if (gr < nrows) {
            size_t base4 = (size_t)gr * 32 + tx * 2;
            ((float4*)h_out)[base4]     = make_float4(acc[i][0], acc[i][1], acc[i][2], acc[i][3]);
            ((float4*)h_out)[base4 + 1] = make_float4(acc[i][4], acc[i][5], acc[i][6], acc[i][7]);
        }
    }
}

// ---------------------------------------------------------------------------
// Gather aggregation: one warp per node.
// agg[d] = sum_{s in in(d)} dinv[s]*dinv[d]*h[s] + dinv[d]^2*h[d] + bias
__global__ __launch_bounds__(256) void gather_kernel(
    const float* __restrict__ h, const float* __restrict__ bias,
    float* __restrict__ agg, int n)
{
    int gid  = blockIdx.x * blockDim.x + threadIdx.x;
    int node = gid >> 5;
    int lane = threadIdx.x & 31;
    if (node >= n) return;

    int beg = g_off[node];
    int end = g_off[node + 1];
    float dd = g_dinv[node];
    float4 acc = make_float4(0.f, 0.f, 0.f, 0.f);

    const float4* hv4 = (const float4*)h;
    int k = beg;
    int s_next = (k < end) ? __ldg(&g_csr[k]) : 0;
    while (k < end) {
        int s = s_next;
        k++;
        if (k < end) s_next = __ldg(&g_csr[k]);
        float w = __ldg(&g_dinv[s]) * dd;
        float4 hv = __ldg(&hv4[(size_t)s * 32 + lane]);
        acc.x += w * hv.x; acc.y += w * hv.y;
        acc.z += w * hv.z; acc.w += w * hv.w;
    }
    // self-loop + bias
    float d2 = dd * dd;
    float4 hv = __ldg(&hv4[(size_t)node * 32 + lane]);
    float4 bb = ((const float4*)bias)[lane];
    acc.x = acc.x + d2 * hv.x + bb.x;
    acc.y = acc.y + d2 * hv.y + bb.y;
    acc.z = acc.z + d2 * hv.z + bb.z;
    acc.w = acc.w + d2 * hv.w + bb.w;
    ((float4*)agg)[(size_t)node * 32 + lane] = acc;
}

// ---------------------------------------------------------------------------
// Per-node head projections: u[n] = h[n] . Wl[0:128], v[n] = h[n] . Wl[128:256]
__global__ __launch_bounds__(256) void uv_kernel(
    const float* __restrict__ h, const float* __restrict__ Wl, int n)
{
    int gid  = blockIdx.x * blockDim.x + threadIdx.x;
    int node = gid >> 5;
    int lane = threadIdx.x & 31;
    if (node >= n) return;
    float4 hv = ((const float4*)h)[(size_t)node * 32 + lane];
    float4 wa = ((const float4*)Wl)[lane];
    float4 wb = ((const float4*)Wl)[32 + lane];
    float su = hv.x * wa.x + hv.y * wa.y + hv.z * wa.z + hv.w * wa.w;
    float sv = hv.x * wb.x + hv.y * wb.y + hv.z * wb.z + hv.w * wb.w;
#pragma unroll
    for (int o = 16; o; o >>= 1) {
        su += __shfl_xor_sync(0xFFFFFFFFu, su, o);
        sv += __shfl_xor_sync(0xFFFFFFFFu, sv, o);
    }
    if (lane == 0) { g_u[node] = su; g_v[node] = sv; }
}

// ---------------------------------------------------------------------------
// Pair prediction: out = sigmoid(u[i] + v[j] + b); one thread per pair.
__global__ __launch_bounds__(256) void pair_kernel(
    const int* __restrict__ pi, const int* __restrict__ pj,
    const float* __restrict__ bl, float* __restrict__ out, int p)
{
    int i = blockIdx.x * blockDim.x + threadIdx.x;
    if (i >= p) return;
    float z = __ldg(&g_u[pi[i]]) + __ldg(&g_v[pj[i]]) + bl[0];
    out[i] = 1.0f / (1.0f + expf(-z));
}

// ---------------------------------------------------------------------------
extern "C" void kernel_launch(void* const* d_in, const int* in_sizes, int n_in,
                              void* d_out, int out_size)
{
    const float* x  = (const float*)d_in[0];
    const int*   ei = (const int*)d_in[1];
    const int*   pi = (const int*)d_in[2];
    const int*   pj = (const int*)d_in[3];
    const float* W1 = (const float*)d_in[4];
    const float* b1 = (const float*)d_in[5];
    const float* W2 = (const float*)d_in[6];
    const float* b2 = (const float*)d_in[7];
    const float* Wl = (const float*)d_in[8];
    const float* bl = (const float*)d_in[9];
    float* out = (float*)d_out;

    int n = in_sizes[0] / HH;
    int e = in_sizes[1] / 2;
    int p = in_sizes[2];
    const int* src  = ei;
    const int* dstp = ei + e;

    float *h_ptr, *aggA, *aggB;
    cudaGetSymbolAddress((void**)&h_ptr, g_h);
    cudaGetSymbolAddress((void**)&aggA,  g_aggA);
    cudaGetSymbolAddress((void**)&aggB,  g_aggB);

    cudaFuncSetAttribute(gemm_kernel, cudaFuncAttributeMaxDynamicSharedMemorySize,
                         GEMM_SMEM);

    int nthr = (n + 255) / 256;
    int ethr = (e + 255) / 256;
    int scanb = (n + 1023) / 1024;

    // degree, dinv, CSR build
    zero_deg_kernel<<<nthr, 256>>>(n);
    deg_count_kernel<<<ethr, 256>>>(dstp, e);
    dinv_kernel<<<nthr, 256>>>(n);
    scan1_kernel<<<scanb, 256>>>(n);
    scan2_kernel<<<1, 256>>>(scanb);
    scan3_kernel<<<scanb, 256>>>(n);
    init_cur_kernel<<<nthr, 256>>>(n);
    scatter_kernel<<<ethr, 256>>>(src, dstp, e);

    int gemm_blocks = (n + 127) / 128;
    int warp_blocks = (int)(((long long)n * 32 + 255) / 256);
    int pair_blocks = (p + 255) / 256;

    // layer 1
    gemm_kernel<<<gemm_blocks, 256, GEMM_SMEM>>>(x, W1, h_ptr, n, 0);
    gather_kernel<<<warp_blocks, 256>>>(h_ptr, b1, aggA, n);

    // layer 2 (relu on input)
    gemm_kernel<<<gemm_blocks, 256, GEMM_SMEM>>>(aggA, W2, h_ptr, n, 1);
    gather_kernel<<<warp_blocks, 256>>>(h_ptr, b2, aggB, n);

    // factorized link head
    uv_kernel<<<warp_blocks, 256>>>(aggB, Wl, n);
    pair_kernel<<<pair_blocks, 256>>>(pi, pj, bl, out, p);
}

// round 8
// speedup vs baseline: 6.0131x; 1.1431x over previous
#include <cuda_runtime.h>
#include <math.h>
#include <stdint.h>

#define NN 100000
#define EE 1600000
#define HH 128
#define SX 68   // smem row stride (floats); 68 mod 32 = 4 -> conflict-free frags

// ---- static device scratch (no allocation allowed) ----
__device__ float g_h[(size_t)NN * HH];     // GEMM output (both layers)
__device__ float g_aggA[(size_t)NN * HH];  // relu(conv1) = layer-2 input
__device__ int   g_deg[NN];
__device__ float g_dinv[NN];
__device__ int   g_off[NN + 1];
__device__ int   g_cur[NN];
__device__ int   g_csr[EE];
__device__ int   g_bsum[512];
__device__ float g_u[NN];
__device__ float g_v[NN];
__device__ float g_Wt1[HH * HH];           // W1 transposed [N][K]
__device__ float g_Wt2[HH * HH];           // W2 transposed [N][K]

// ---------------------------------------------------------------------------
__global__ void zero_deg_kernel(int n) {
    int i = blockIdx.x * blockDim.x + threadIdx.x;
    if (i < n) g_deg[i] = 0;
}

__global__ void deg_count_kernel(const int* __restrict__ dst, int e) {
    int i = blockIdx.x * blockDim.x + threadIdx.x;
    if (i < e) atomicAdd(&g_deg[dst[i]], 1);
}

__global__ void dinv_kernel(int n) {
    int i = blockIdx.x * blockDim.x + threadIdx.x;
    if (i < n) g_dinv[i] = rsqrtf((float)g_deg[i] + 1.0f);
}

__global__ void transpose_w_kernel(const float* __restrict__ W,
                                   float* __restrict__ Wt) {
    int i = blockIdx.x * blockDim.x + threadIdx.x;  // 16384
    int k = i >> 7, n = i & 127;
    Wt[n * HH + k] = W[k * HH + n];
}

// ---- exclusive prefix scan of deg into off ----
__global__ __launch_bounds__(256) void scan1_kernel(int n) {
    __shared__ int wsum[8];
    __shared__ int woff[8];
    int t = threadIdx.x;
    int idx0 = blockIdx.x * 1024 + t * 4;
    int v[4];
#pragma unroll
    for (int q = 0; q < 4; q++) {
        int i = idx0 + q;
        v[q] = (i < n) ? g_deg[i] : 0;
    }
    v[1] += v[0]; v[2] += v[1]; v[3] += v[2];
    int tsum = v[3];
    int lane = t & 31, wid = t >> 5;
    int x = tsum;
#pragma unroll
    for (int o = 1; o < 32; o <<= 1) {
        int y = __shfl_up_sync(0xFFFFFFFFu, x, o);
        if (lane >= o) x += y;
    }
    if (lane == 31) wsum[wid] = x;
    __syncthreads();
    if (t == 0) {
        int a = 0;
        for (int w = 0; w < 8; w++) { woff[w] = a; a += wsum[w]; }
    }
    __syncthreads();
    int ex = x - tsum + woff[wid];
#pragma unroll
    for (int q = 0; q < 4; q++) {
        int i = idx0 + q;
        if (i < n) g_off[i + 1] = ex + v[q];
    }
    if (t == 255) g_bsum[blockIdx.x] = ex + tsum;
}

__global__ __launch_bounds__(256) void scan2_kernel(int nb) {
    __shared__ int ws[8];
    int t = threadIdx.x;
    int x = (t < nb) ? g_bsum[t] : 0;
    int lane = t & 31, wid = t >> 5;
#pragma unroll
    for (int o = 1; o < 32; o <<= 1) {
        int y = __shfl_up_sync(0xFFFFFFFFu, x, o);
        if (lane >= o) x += y;
    }
    if (lane == 31) ws[wid] = x;
    __syncthreads();
    int add = 0;
    for (int w = 0; w < wid; w++) add += ws[w];
    x += add;
    if (t < nb) g_bsum[t] = x;
}

__global__ __launch_bounds__(256) void scan3_kernel(int n) {
    int b = blockIdx.x;
    int add = (b == 0) ? 0 : g_bsum[b - 1];
    int idx0 = b * 1024 + threadIdx.x * 4;
    if (b == 0 && threadIdx.x == 0) g_off[0] = 0;
#pragma unroll
    for (int q = 0; q < 4; q++) {
        int i = idx0 + q;
        if (i < n) g_off[i + 1] += add;
    }
}

__global__ void init_cur_kernel(int n) {
    int i = blockIdx.x * blockDim.x + threadIdx.x;
    if (i < n) g_cur[i] = g_off[i];
}

__global__ void scatter_kernel(const int* __restrict__ src,
                               const int* __restrict__ dst, int e) {
    int i = blockIdx.x * blockDim.x + threadIdx.x;
    if (i < e) {
        int d = dst[i];
        int pos = atomicAdd(&g_cur[d], 1);
        g_csr[pos] = src[i];
    }
}

// ---------------------------------------------------------------------------
// 3xTF32 mma.sync GEMM: D = X @ Wt^T (= X @ W), fp32-equivalent precision.
// CTA: 128x128 tile, 8 warps (4m x 2n), warp: 32x64, K chunked by 64.
#define TG_SMEM (4 * 128 * SX * 4)

__device__ __forceinline__ void split_tf32(float x, uint32_t& hi, uint32_t& lo) {
    asm("cvt.rna.tf32.f32 %0, %1;" : "=r"(hi) : "f"(x));
    float r = x - __uint_as_float(hi);
    asm("cvt.rna.tf32.f32 %0, %1;" : "=r"(lo) : "f"(r));
}

#define MMA_TF32(c, a, b0, b1)                                              \
    asm volatile("mma.sync.aligned.m16n8k8.row.col.f32.tf32.tf32.f32 "      \
                 "{%0,%1,%2,%3}, {%4,%5,%6,%7}, {%8,%9}, {%0,%1,%2,%3};"    \
                 : "+f"((c)[0]), "+f"((c)[1]), "+f"((c)[2]), "+f"((c)[3])   \
                 : "r"((a)[0]), "r"((a)[1]), "r"((a)[2]), "r"((a)[3]),      \
                   "r"(b0), "r"(b1))

__global__ __launch_bounds__(256, 1)
void tgemm_kernel(const float* __restrict__ X, const float* __restrict__ Wt,
                  float* __restrict__ h_out, int nrows)
{
    extern __shared__ float smem[];
    float* Xh = smem;
    float* Xl = Xh + 128 * SX;
    float* Wh = Xl + 128 * SX;
    float* Wlo = Wh + 128 * SX;

    int t = threadIdx.x;
    int wid = t >> 5, lid = t & 31;
    int gid = lid >> 2, ctid = lid & 3;
    int wm = wid >> 1, wn = wid & 1;
    int row0 = blockIdx.x * 128;

    float acc[2][8][4];
#pragma unroll
    for (int mi = 0; mi < 2; mi++)
#pragma unroll
        for (int ni = 0; ni < 8; ni++)
#pragma unroll
            for (int q = 0; q < 4; q++) acc[mi][ni][q] = 0.f;

    for (int c0 = 0; c0 < HH; c0 += 64) {
        __syncthreads();
        // stage X and Wt chunk, split into tf32 hi/lo
        for (int idx = t; idx < 2048; idx += 256) {
            int r = idx >> 4, q = idx & 15;
            int gr = row0 + r;
            float4 v = make_float4(0.f, 0.f, 0.f, 0.f);
            if (gr < nrows) v = ((const float4*)X)[(size_t)gr * 32 + (c0 >> 2) + q];
            uint32_t h4[4], l4[4];
            split_tf32(v.x, h4[0], l4[0]); split_tf32(v.y, h4[1], l4[1]);
            split_tf32(v.z, h4[2], l4[2]); split_tf32(v.w, h4[3], l4[3]);
            *(uint4*)&Xh[r * SX + q * 4] = *(uint4*)h4;
            *(uint4*)&Xl[r * SX + q * 4] = *(uint4*)l4;

            float4 w = ((const float4*)Wt)[r * 32 + (c0 >> 2) + q];
            split_tf32(w.x, h4[0], l4[0]); split_tf32(w.y, h4[1], l4[1]);
            split_tf32(w.z, h4[2], l4[2]); split_tf32(w.w, h4[3], l4[3]);
            *(uint4*)&Wh[r * SX + q * 4] = *(uint4*)h4;
            *(uint4*)&Wlo[r * SX + q * 4] = *(uint4*)l4;
        }
        __syncthreads();

        const uint32_t* xh = (const uint32_t*)Xh;
        const uint32_t* xl = (const uint32_t*)Xl;
        const uint32_t* wh = (const uint32_t*)Wh;
        const uint32_t* wl = (const uint32_t*)Wlo;

#pragma unroll
        for (int kk = 0; kk < 64; kk += 8) {
            uint32_t ah[2][4], al[2][4];
#pragma unroll
            for (int mi = 0; mi < 2; mi++) {
                int rb = (wm * 32 + mi * 16 + gid) * SX + kk + ctid;
                ah[mi][0] = xh[rb];            ah[mi][1] = xh[rb + 8 * SX];
                ah[mi][2] = xh[rb + 4];        ah[mi][3] = xh[rb + 8 * SX + 4];
                al[mi][0] = xl[rb];            al[mi][1] = xl[rb + 8 * SX];
                al[mi][2] = xl[rb + 4];        al[mi][3] = xl[rb + 8 * SX + 4];
            }
#pragma unroll
            for (int ni = 0; ni < 8; ni++) {
                int nb = (wn * 64 + ni * 8 + gid) * SX + kk + ctid;
                uint32_t bh0 = wh[nb], bh1 = wh[nb + 4];
                uint32_t bl0 = wl[nb], bl1 = wl[nb + 4];
#pragma unroll
                for (int mi = 0; mi < 2; mi++) {
                    MMA_TF32(acc[mi][ni], ah[mi], bh0, bh1);
                    MMA_TF32(acc[mi][ni], ah[mi], bl0, bl1);
                    MMA_TF32(acc[mi][ni], al[mi], bh0, bh1);
                }
            }
        }
    }

    // epilogue: direct global stores
#pragma unroll
    for (int mi = 0; mi < 2; mi++) {
        int gr = row0 + wm * 32 + mi * 16 + gid;
#pragma unroll
        for (int ni = 0; ni < 8; ni++) {
            int gc = wn * 64 + ni * 8 + 2 * ctid;
            if (gr < nrows)
                *(float2*)&h_out[(size_t)gr * HH + gc] =
                    make_float2(acc[mi][ni][0], acc[mi][ni][1]);
            if (gr + 8 < nrows)
                *(float2*)&h_out[(size_t)(gr + 8) * HH + gc] =
                    make_float2(acc[mi][ni][2], acc[mi][ni][3]);
        }
    }
}

// ---------------------------------------------------------------------------
// Gather aggregation, layer 1: agg = relu(sum msgs + self + bias)
__global__ __launch_bounds__(256) void gather_relu_kernel(
    const float* __restrict__ h, const float* __restrict__ bias,
    float* __restrict__ agg, int n)
{
    int gid  = blockIdx.x * blockDim.x + threadIdx.x;
    int node = gid >> 5;
    int lane = threadIdx.x & 31;
    if (node >= n) return;

    int beg = g_off[node];
    int end = g_off[node + 1];
    float dd = g_dinv[node];
    float4 acc = make_float4(0.f, 0.f, 0.f, 0.f);
    const float4* hv4 = (const float4*)h;
    for (int k = beg; k < end; k++) {
        int s = __ldg(&g_csr[k]);
        float w = __ldg(&g_dinv[s]) * dd;
        float4 hv = __ldg(&hv4[(size_t)s * 32 + lane]);
        acc.x += w * hv.x; acc.y += w * hv.y;
        acc.z += w * hv.z; acc.w += w * hv.w;
    }
    float d2 = dd * dd;
    float4 hv = __ldg(&hv4[(size_t)node * 32 + lane]);
    float4 bb = ((const float4*)bias)[lane];
    acc.x = fmaxf(acc.x + d2 * hv.x + bb.x, 0.f);
    acc.y = fmaxf(acc.y + d2 * hv.y + bb.y, 0.f);
    acc.z = fmaxf(acc.z + d2 * hv.z + bb.z, 0.f);
    acc.w = fmaxf(acc.w + d2 * hv.w + bb.w, 0.f);
    ((float4*)agg)[(size_t)node * 32 + lane] = acc;
}

// Gather aggregation, layer 2, fused link head: writes only u[n], v[n].
__global__ __launch_bounds__(256) void gather_head_kernel(
    const float* __restrict__ h, const float* __restrict__ bias,
    const float* __restrict__ Wl, int n)
{
    int gid  = blockIdx.x * blockDim.x + threadIdx.x;
    int node = gid >> 5;
    int lane = threadIdx.x & 31;
    if (node >= n) return;

    int beg = g_off[node];
    int end = g_off[node + 1];
    float dd = g_dinv[node];
    float4 acc = make_float4(0.f, 0.f, 0.f, 0.f);
    const float4* hv4 = (const float4*)h;
    for (int k = beg; k < end; k++) {
        int s = __ldg(&g_csr[k]);
        float w = __ldg(&g_dinv[s]) * dd;
        float4 hv = __ldg(&hv4[(size_t)s * 32 + lane]);
        acc.x += w * hv.x; acc.y += w * hv.y;
        acc.z += w * hv.z; acc.w += w * hv.w;
    }
    float d2 = dd * dd;
    float4 hv = __ldg(&hv4[(size_t)node * 32 + lane]);
    float4 bb = ((const float4*)bias)[lane];
    acc.x += d2 * hv.x + bb.x;
    acc.y += d2 * hv.y + bb.y;
    acc.z += d2 * hv.z + bb.z;
    acc.w += d2 * hv.w + bb.w;

    float4 wa = ((const float4*)Wl)[lane];
    float4 wb = ((const float4*)Wl)[32 + lane];
    float su = acc.x * wa.x + acc.y * wa.y + acc.z * wa.z + acc.w * wa.w;
    float sv = acc.x * wb.x + acc.y * wb.y + acc.z * wb.z + acc.w * wb.w;
#pragma unroll
    for (int o = 16; o; o >>= 1) {
        su += __shfl_xor_sync(0xFFFFFFFFu, su, o);
        sv += __shfl_xor_sync(0xFFFFFFFFu, sv, o);
    }
    if (lane == 0) { g_u[node] = su; g_v[node] = sv; }
}

// ---------------------------------------------------------------------------
__global__ __launch_bounds__(256) void pair_kernel(
    const int* __restrict__ pi, const int* __restrict__ pj,
    const float* __restrict__ bl, float* __restrict__ out, int p)
{
    int i = blockIdx.x * blockDim.x + threadIdx.x;
    if (i >= p) return;
    float z = __ldg(&g_u[pi[i]]) + __ldg(&g_v[pj[i]]) + bl[0];
    out[i] = 1.0f / (1.0f + expf(-z));
}

// ---------------------------------------------------------------------------
extern "C" void kernel_launch(void* const* d_in, const int* in_sizes, int n_in,
                              void* d_out, int out_size)
{
    const float* x  = (const float*)d_in[0];
    const int*   ei = (const int*)d_in[1];
    const int*   pi = (const int*)d_in[2];
    const int*   pj = (const int*)d_in[3];
    const float* W1 = (const float*)d_in[4];
    const float* b1 = (const float*)d_in[5];
    const float* W2 = (const float*)d_in[6];
    const float* b2 = (const float*)d_in[7];
    const float* Wl = (const float*)d_in[8];
    const float* bl = (const float*)d_in[9];
    float* out = (float*)d_out;

    int n = in_sizes[0] / HH;
    int e = in_sizes[1] / 2;
    int p = in_sizes[2];
    const int* src  = ei;
    const int* dstp = ei + e;

    float *h_ptr, *aggA, *wt1, *wt2;
    cudaGetSymbolAddress((void**)&h_ptr, g_h);
    cudaGetSymbolAddress((void**)&aggA,  g_aggA);
    cudaGetSymbolAddress((void**)&wt1,   g_Wt1);
    cudaGetSymbolAddress((void**)&wt2,   g_Wt2);

    cudaFuncSetAttribute(tgemm_kernel, cudaFuncAttributeMaxDynamicSharedMemorySize,
                         TG_SMEM);

    int nthr = (n + 255) / 256;
    int ethr = (e + 255) / 256;
    int scanb = (n + 1023) / 1024;

    // degree, dinv, CSR build, weight transposes
    zero_deg_kernel<<<nthr, 256>>>(n);
    deg_count_kernel<<<ethr, 256>>>(dstp, e);
    dinv_kernel<<<nthr, 256>>>(n);
    scan1_kernel<<<scanb, 256>>>(n);
    scan2_kernel<<<1, 256>>>(scanb);
    scan3_kernel<<<scanb, 256>>>(n);
    init_cur_kernel<<<nthr, 256>>>(n);
    scatter_kernel<<<ethr, 256>>>(src, dstp, e);
    transpose_w_kernel<<<64, 256>>>(W1, wt1);
    transpose_w_kernel<<<64, 256>>>(W2, wt2);

    int gemm_blocks = (n + 127) / 128;
    int warp_blocks = (int)(((long long)n * 32 + 255) / 256);
    int pair_blocks = (p + 255) / 256;

    // layer 1
    tgemm_kernel<<<gemm_blocks, 256, TG_SMEM>>>(x, wt1, h_ptr, n);
    gather_relu_kernel<<<warp_blocks, 256>>>(h_ptr, b1, aggA, n);

    // layer 2 (input already relu'd) + fused head
    tgemm_kernel<<<gemm_blocks, 256, TG_SMEM>>>(aggA, wt2, h_ptr, n);
    gather_head_kernel<<<warp_blocks, 256>>>(h_ptr, b2, Wl, n);

    // pair prediction
    pair_kernel<<<pair_blocks, 256>>>(pi, pj, bl, out, p);
}

// round 9
// speedup vs baseline: 6.3911x; 1.0629x over previous
#include <cuda_runtime.h>
#include <math.h>
#include <stdint.h>

#define NN 100000
#define EE 1600000
#define HH 128
#define ST 68   // smem row stride in uint32 (64 pairs + pad); 68%32=4 -> conflict-free

// ---- static device scratch (no allocation allowed) ----
__device__ float g_h[(size_t)NN * HH];     // GEMM output (both layers)
__device__ float g_aggA[(size_t)NN * HH];  // relu(conv1) = layer-2 input
__device__ int   g_deg[NN];
__device__ float g_dinv[NN];
__device__ int   g_off[NN + 1];
__device__ int   g_cur[NN];
__device__ int   g_csr[EE];
__device__ int   g_bsum[512];
__device__ float g_u[NN];
__device__ float g_v[NN];
__device__ float g_Wt1[HH * HH];           // W1 transposed [N][K]
__device__ float g_Wt2[HH * HH];           // W2 transposed [N][K]

// ---------------------------------------------------------------------------
__global__ void zero_deg_kernel(int n) {
    int i = blockIdx.x * blockDim.x + threadIdx.x;
    if (i < n) g_deg[i] = 0;
}

__global__ void deg_count_kernel(const int* __restrict__ dst, int e) {
    int i = blockIdx.x * blockDim.x + threadIdx.x;
    if (i < e) atomicAdd(&g_deg[dst[i]], 1);
}

__global__ void transpose_w_kernel(const float* __restrict__ W,
                                   float* __restrict__ Wt) {
    int i = blockIdx.x * blockDim.x + threadIdx.x;  // 16384
    int k = i >> 7, n = i & 127;
    Wt[n * HH + k] = W[k * HH + n];
}

// ---- exclusive prefix scan of deg into off (also computes dinv) ----
__global__ __launch_bounds__(256) void scan1_kernel(int n) {
    __shared__ int wsum[8];
    __shared__ int woff[8];
    int t = threadIdx.x;
    int idx0 = blockIdx.x * 1024 + t * 4;
    int v[4];
#pragma unroll
    for (int q = 0; q < 4; q++) {
        int i = idx0 + q;
        v[q] = (i < n) ? g_deg[i] : 0;
        if (i < n) g_dinv[i] = rsqrtf((float)v[q] + 1.0f);
    }
    v[1] += v[0]; v[2] += v[1]; v[3] += v[2];
    int tsum = v[3];
    int lane = t & 31, wid = t >> 5;
    int x = tsum;
#pragma unroll
    for (int o = 1; o < 32; o <<= 1) {
        int y = __shfl_up_sync(0xFFFFFFFFu, x, o);
        if (lane >= o) x += y;
    }
    if (lane == 31) wsum[wid] = x;
    __syncthreads();
    if (t == 0) {
        int a = 0;
        for (int w = 0; w < 8; w++) { woff[w] = a; a += wsum[w]; }
    }
    __syncthreads();
    int ex = x - tsum + woff[wid];
#pragma unroll
    for (int q = 0; q < 4; q++) {
        int i = idx0 + q;
        if (i < n) g_off[i + 1] = ex + v[q];
    }
    if (t == 255) g_bsum[blockIdx.x] = ex + tsum;
}

__global__ __launch_bounds__(256) void scan2_kernel(int nb) {
    __shared__ int ws[8];
    int t = threadIdx.x;
    int x = (t < nb) ? g_bsum[t] : 0;
    int lane = t & 31, wid = t >> 5;
#pragma unroll
    for (int o = 1; o < 32; o <<= 1) {
        int y = __shfl_up_sync(0xFFFFFFFFu, x, o);
        if (lane >= o) x += y;
    }
    if (lane == 31) ws[wid] = x;
    __syncthreads();
    int add = 0;
    for (int w = 0; w < wid; w++) add += ws[w];
    x += add;
    if (t < nb) g_bsum[t] = x;
}

__global__ __launch_bounds__(256) void scan3_kernel(int n) {
    int b = blockIdx.x;
    int add = (b == 0) ? 0 : g_bsum[b - 1];
    int idx0 = b * 1024 + threadIdx.x * 4;
    if (b == 0 && threadIdx.x == 0) { g_off[0] = 0; g_cur[0] = 0; }
#pragma unroll
    for (int q = 0; q < 4; q++) {
        int i = idx0 + q;
        if (i < n) {
            int o = g_off[i + 1] + add;
            g_off[i + 1] = o;
            if (i + 1 < n) g_cur[i + 1] = o;
        }
    }
}

__global__ void scatter_kernel(const int* __restrict__ src,
                               const int* __restrict__ dst, int e) {
    int i = blockIdx.x * blockDim.x + threadIdx.x;
    if (i < e) {
        int d = dst[i];
        int pos = atomicAdd(&g_cur[d], 1);
        g_csr[pos] = src[i];
    }
}

// ---------------------------------------------------------------------------
// 3xBF16 mma.sync GEMM (m16n8k16): D = X @ Wt^T (= X @ W).
// x = hi + lo in bf16 -> D = Ah.Bh + Ah.Bl + Al.Bh (lo.lo term ~2^-17 dropped).
// CTA: 128x128 tile, 8 warps (4m x 2n), warp: 32x64, single K=128 pass.
#define TG_SMEM (4 * 128 * ST * 4)

// pack two floats (x0 -> low bf16, x1 -> high bf16)
__device__ __forceinline__ uint32_t pack_bf16x2(float x0, float x1) {
    uint32_t r;
    asm("cvt.rn.bf16x2.f32 %0, %1, %2;" : "=r"(r) : "f"(x1), "f"(x0));
    return r;
}

#define MMA_BF16(c, a, b0, b1)                                               \
    asm volatile("mma.sync.aligned.m16n8k16.row.col.f32.bf16.bf16.f32 "      \
                 "{%0,%1,%2,%3}, {%4,%5,%6,%7}, {%8,%9}, {%0,%1,%2,%3};"     \
                 : "+f"((c)[0]), "+f"((c)[1]), "+f"((c)[2]), "+f"((c)[3])    \
                 : "r"((a)[0]), "r"((a)[1]), "r"((a)[2]), "r"((a)[3]),       \
                   "r"(b0), "r"(b1))

__global__ __launch_bounds__(256, 1)
void tgemm_kernel(const float* __restrict__ X, const float* __restrict__ Wt,
                  float* __restrict__ h_out, int nrows)
{
    extern __shared__ uint32_t smem[];
    uint32_t* Xh = smem;                 // [128][ST] bf16x2 pairs (hi)
    uint32_t* Xl = Xh + 128 * ST;        // (lo)
    uint32_t* Wh = Xl + 128 * ST;
    uint32_t* Wl = Wh + 128 * ST;

    int t = threadIdx.x;
    int wid = t >> 5, lid = t & 31;
    int gid = lid >> 2, ctid = lid & 3;
    int wm = wid >> 1, wn = wid & 1;
    int row0 = blockIdx.x * 128;

    // stage X and Wt, split into bf16 hi/lo pairs
    for (int idx = t; idx < 4096; idx += 256) {
        int r = idx >> 5, q = idx & 31;      // q: float4 index (4 k-values)
        int gr = row0 + r;
        float4 v = make_float4(0.f, 0.f, 0.f, 0.f);
        if (gr < nrows) v = ((const float4*)X)[(size_t)gr * 32 + q];
        uint32_t hp0 = pack_bf16x2(v.x, v.y);
        uint32_t hp1 = pack_bf16x2(v.z, v.w);
        float f0 = __uint_as_float(hp0 << 16);
        float f1 = __uint_as_float(hp0 & 0xFFFF0000u);
        float f2 = __uint_as_float(hp1 << 16);
        float f3 = __uint_as_float(hp1 & 0xFFFF0000u);
        Xh[r * ST + 2 * q]     = hp0;
        Xh[r * ST + 2 * q + 1] = hp1;
        Xl[r * ST + 2 * q]     = pack_bf16x2(v.x - f0, v.y - f1);
        Xl[r * ST + 2 * q + 1] = pack_bf16x2(v.z - f2, v.w - f3);

        float4 w = ((const float4*)Wt)[r * 32 + q];
        hp0 = pack_bf16x2(w.x, w.y);
        hp1 = pack_bf16x2(w.z, w.w);
        f0 = __uint_as_float(hp0 << 16);
        f1 = __uint_as_float(hp0 & 0xFFFF0000u);
        f2 = __uint_as_float(hp1 << 16);
        f3 = __uint_as_float(hp1 & 0xFFFF0000u);
        Wh[r * ST + 2 * q]     = hp0;
        Wh[r * ST + 2 * q + 1] = hp1;
        Wl[r * ST + 2 * q]     = pack_bf16x2(w.x - f0, w.y - f1);
        Wl[r * ST + 2 * q + 1] = pack_bf16x2(w.z - f2, w.w - f3);
    }
    __syncthreads();

    float acc[2][8][4];
#pragma unroll
    for (int mi = 0; mi < 2; mi++)
#pragma unroll
        for (int ni = 0; ni < 8; ni++)
#pragma unroll
            for (int q = 0; q < 4; q++) acc[mi][ni][q] = 0.f;

#pragma unroll
    for (int ks = 0; ks < 8; ks++) {         // 8 steps of K=16 (8 uint32 pairs)
        int kb = ks * 8 + ctid;
        uint32_t ah[2][4], al[2][4];
#pragma unroll
        for (int mi = 0; mi < 2; mi++) {
            int rb = (wm * 32 + mi * 16 + gid) * ST + kb;
            ah[mi][0] = Xh[rb];            ah[mi][1] = Xh[rb + 8 * ST];
            ah[mi][2] = Xh[rb + 4];        ah[mi][3] = Xh[rb + 8 * ST + 4];
            al[mi][0] = Xl[rb];            al[mi][1] = Xl[rb + 8 * ST];
            al[mi][2] = Xl[rb + 4];        al[mi][3] = Xl[rb + 8 * ST + 4];
        }
#pragma unroll
        for (int ni = 0; ni < 8; ni++) {
            int nb = (wn * 64 + ni * 8 + gid) * ST + kb;
            uint32_t bh0 = Wh[nb], bh1 = Wh[nb + 4];
            uint32_t bl0 = Wl[nb], bl1 = Wl[nb + 4];
#pragma unroll
            for (int mi = 0; mi < 2; mi++) {
                MMA_BF16(acc[mi][ni], ah[mi], bh0, bh1);
                MMA_BF16(acc[mi][ni], ah[mi], bl0, bl1);
                MMA_BF16(acc[mi][ni], al[mi], bh0, bh1);
            }
        }
    }

    // epilogue: direct global stores
#pragma unroll
    for (int mi = 0; mi < 2; mi++) {
        int gr = row0 + wm * 32 + mi * 16 + gid;
#pragma unroll
        for (int ni = 0; ni < 8; ni++) {
            int gc = wn * 64 + ni * 8 + 2 * ctid;
            if (gr < nrows)
                *(float2*)&h_out[(size_t)gr * HH + gc] =
                    make_float2(acc[mi][ni][0], acc[mi][ni][1]);
            if (gr + 8 < nrows)
                *(float2*)&h_out[(size_t)(gr + 8) * HH + gc] =
                    make_float2(acc[mi][ni][2], acc[mi][ni][3]);
        }
    }
}

// ---------------------------------------------------------------------------
// Gather aggregation, layer 1: agg = relu(sum msgs + self + bias)
__global__ __launch_bounds__(256) void gather_relu_kernel(
    const float* __restrict__ h, const float* __restrict__ bias,
    float* __restrict__ agg, int n)
{
    int gid  = blockIdx.x * blockDim.x + threadIdx.x;
    int node = gid >> 5;
    int lane = threadIdx.x & 31;
    if (node >= n) return;

    int beg = g_off[node];
    int end = g_off[node + 1];
    float dd = g_dinv[node];
    float4 acc = make_float4(0.f, 0.f, 0.f, 0.f);
    const float4* hv4 = (const float4*)h;
    for (int k = beg; k < end; k++) {
        int s = __ldg(&g_csr[k]);
        float w = __ldg(&g_dinv[s]) * dd;
        float4 hv = __ldg(&hv4[(size_t)s * 32 + lane]);
        acc.x += w * hv.x; acc.y += w * hv.y;
        acc.z += w * hv.z; acc.w += w * hv.w;
    }
    float d2 = dd * dd;
    float4 hv = __ldg(&hv4[(size_t)node * 32 + lane]);
    float4 bb = ((const float4*)bias)[lane];
    acc.x = fmaxf(acc.x + d2 * hv.x + bb.x, 0.f);
    acc.y = fmaxf(acc.y + d2 * hv.y + bb.y, 0.f);
    acc.z = fmaxf(acc.z + d2 * hv.z + bb.z, 0.f);
    acc.w = fmaxf(acc.w + d2 * hv.w + bb.w, 0.f);
    ((float4*)agg)[(size_t)node * 32 + lane] = acc;
}

// Gather aggregation, layer 2, fused link head: writes only u[n], v[n].
__global__ __launch_bounds__(256) void gather_head_kernel(
    const float* __restrict__ h, const float* __restrict__ bias,
    const float* __restrict__ Wl, int n)
{
    int gid  = blockIdx.x * blockDim.x + threadIdx.x;
    int node = gid >> 5;
    int lane = threadIdx.x & 31;
    if (node >= n) return;

    int beg = g_off[node];
    int end = g_off[node + 1];
    float dd = g_dinv[node];
    float4 acc = make_float4(0.f, 0.f, 0.f, 0.f);
    const float4* hv4 = (const float4*)h;
    for (int k = beg; k < end; k++) {
        int s = __ldg(&g_csr[k]);
        float w = __ldg(&g_dinv[s]) * dd;
        float4 hv = __ldg(&hv4[(size_t)s * 32 + lane]);
        acc.x += w * hv.x; acc.y += w * hv.y;
        acc.z += w * hv.z; acc.w += w * hv.w;
    }
    float d2 = dd * dd;
    float4 hv = __ldg(&hv4[(size_t)node * 32 + lane]);
    float4 bb = ((const float4*)bias)[lane];
    acc.x += d2 * hv.x + bb.x;
    acc.y += d2 * hv.y + bb.y;
    acc.z += d2 * hv.z + bb.z;
    acc.w += d2 * hv.w + bb.w;

    float4 wa = ((const float4*)Wl)[lane];
    float4 wb = ((const float4*)Wl)[32 + lane];
    float su = acc.x * wa.x + acc.y * wa.y + acc.z * wa.z + acc.w * wa.w;
    float sv = acc.x * wb.x + acc.y * wb.y + acc.z * wb.z + acc.w * wb.w;
#pragma unroll
    for (int o = 16; o; o >>= 1) {
        su += __shfl_xor_sync(0xFFFFFFFFu, su, o);
        sv += __shfl_xor_sync(0xFFFFFFFFu, sv, o);
    }
    if (lane == 0) { g_u[node] = su; g_v[node] = sv; }
}

// ---------------------------------------------------------------------------
__global__ __launch_bounds__(256) void pair_kernel(
    const int* __restrict__ pi, const int* __restrict__ pj,
    const float* __restrict__ bl, float* __restrict__ out, int p)
{
    int i = blockIdx.x * blockDim.x + threadIdx.x;
    if (i >= p) return;
    float z = __ldg(&g_u[pi[i]]) + __ldg(&g_v[pj[i]]) + bl[0];
    out[i] = 1.0f / (1.0f + expf(-z));
}

// ---------------------------------------------------------------------------
extern "C" void kernel_launch(void* const* d_in, const int* in_sizes, int n_in,
                              void* d_out, int out_size)
{
    const float* x  = (const float*)d_in[0];
    const int*   ei = (const int*)d_in[1];
    const int*   pi = (const int*)d_in[2];
    const int*   pj = (const int*)d_in[3];
    const float* W1 = (const float*)d_in[4];
    const float* b1 = (const float*)d_in[5];
    const float* W2 = (const float*)d_in[6];
    const float* b2 = (const float*)d_in[7];
    const float* Wl = (const float*)d_in[8];
    const float* bl = (const float*)d_in[9];
    float* out = (float*)d_out;

    int n = in_sizes[0] / HH;
    int e = in_sizes[1] / 2;
    int p = in_sizes[2];
    const int* src  = ei;
    const int* dstp = ei + e;

    float *h_ptr, *aggA, *wt1, *wt2;
    cudaGetSymbolAddress((void**)&h_ptr, g_h);
    cudaGetSymbolAddress((void**)&aggA,  g_aggA);
    cudaGetSymbolAddress((void**)&wt1,   g_Wt1);
    cudaGetSymbolAddress((void**)&wt2,   g_Wt2);

    cudaFuncSetAttribute(tgemm_kernel, cudaFuncAttributeMaxDynamicSharedMemorySize,
                         TG_SMEM);

    int nthr = (n + 255) / 256;
    int ethr = (e + 255) / 256;
    int scanb = (n + 1023) / 1024;

    // degree, dinv, CSR build, weight transposes
    zero_deg_kernel<<<nthr, 256>>>(n);
    deg_count_kernel<<<ethr, 256>>>(dstp, e);
    scan1_kernel<<<scanb, 256>>>(n);
    scan2_kernel<<<1, 256>>>(scanb);
    scan3_kernel<<<scanb, 256>>>(n);
    scatter_kernel<<<ethr, 256>>>(src, dstp, e);
    transpose_w_kernel<<<64, 256>>>(W1, wt1);
    transpose_w_kernel<<<64, 256>>>(W2, wt2);

    int gemm_blocks = (n + 127) / 128;
    int warp_blocks = (int)(((long long)n * 32 + 255) / 256);
    int pair_blocks = (p + 255) / 256;

    // layer 1
    tgemm_kernel<<<gemm_blocks, 256, TG_SMEM>>>(x, wt1, h_ptr, n);
    gather_relu_kernel<<<warp_blocks, 256>>>(h_ptr, b1, aggA, n);

    // layer 2 (input already relu'd) + fused head
    tgemm_kernel<<<gemm_blocks, 256, TG_SMEM>>>(aggA, wt2, h_ptr, n);
    gather_head_kernel<<<warp_blocks, 256>>>(h_ptr, b2, Wl, n);

    // pair prediction
    pair_kernel<<<pair_blocks, 256>>>(pi, pj, bl, out, p);
}